// round 1
// baseline (speedup 1.0000x reference)
#include <cuda_runtime.h>

// Problem constants (fixed by reference: B=32, N=4096, D=128, E=24576)
#define BB 32
#define NN 4096
#define DD 128
#define EE 24576
#define BN (BB * NN)

// Scratch (device globals: no allocation allowed in kernel_launch)
__device__ int   g_counts[NN];
__device__ int   g_offsets[NN + 1];
__device__ int   g_cursor[NN];
__device__ int   g_perm[EE];
__device__ float g_ssrc[BN];
__device__ float g_sdst[BN];

// ---------------------------------------------------------------------------
// CSR build over dst (deterministic: scatter with atomics, then per-bucket
// sort by edge id so accumulation order is reproducible across replays).
// ---------------------------------------------------------------------------

__global__ void k_zero_counts() {
    int i = blockIdx.x * blockDim.x + threadIdx.x;
    if (i < NN) g_counts[i] = 0;
}

__global__ void k_hist(const int* __restrict__ dst) {
    int e = blockIdx.x * blockDim.x + threadIdx.x;
    if (e < EE) atomicAdd(&g_counts[dst[e]], 1);
}

// Single-block exclusive scan of 4096 counts (1024 threads x 4 elements).
__global__ void k_scan() {
    __shared__ int sh[1024];
    int t = threadIdx.x;
    int base = t * 4;
    int v0 = g_counts[base + 0];
    int v1 = g_counts[base + 1];
    int v2 = g_counts[base + 2];
    int v3 = g_counts[base + 3];
    int s = v0 + v1 + v2 + v3;
    sh[t] = s;
    __syncthreads();
    for (int off = 1; off < 1024; off <<= 1) {
        int add = (t >= off) ? sh[t - off] : 0;
        __syncthreads();
        sh[t] += add;
        __syncthreads();
    }
    int run = sh[t] - s;  // exclusive prefix for this thread's 4 slots
    g_offsets[base + 0] = run; g_cursor[base + 0] = run; run += v0;
    g_offsets[base + 1] = run; g_cursor[base + 1] = run; run += v1;
    g_offsets[base + 2] = run; g_cursor[base + 2] = run; run += v2;
    g_offsets[base + 3] = run; g_cursor[base + 3] = run; run += v3;
    if (t == 1023) g_offsets[NN] = run;  // == EE
}

__global__ void k_scatter(const int* __restrict__ dst) {
    int e = blockIdx.x * blockDim.x + threadIdx.x;
    if (e < EE) {
        int pos = atomicAdd(&g_cursor[dst[e]], 1);
        g_perm[pos] = e;
    }
}

// Per-node insertion sort of its bucket (avg 6 elements) -> deterministic order.
__global__ void k_sort_buckets() {
    int n = blockIdx.x * blockDim.x + threadIdx.x;
    if (n >= NN) return;
    int lo = g_offsets[n], hi = g_offsets[n + 1];
    for (int i = lo + 1; i < hi; i++) {
        int key = g_perm[i];
        int j = i - 1;
        while (j >= lo && g_perm[j] > key) {
            g_perm[j + 1] = g_perm[j];
            j--;
        }
        g_perm[j + 1] = key;
    }
}

// ---------------------------------------------------------------------------
// Per-node projections: ssrc[b,n] = <x[b,n], Ws>, sdst[b,n] = <x[b,n], Wd>.
// One warp per row; each lane owns one float4 (D=128 = 32 lanes * 4).
// ---------------------------------------------------------------------------
__global__ void k_dots(const float4* __restrict__ x4, const float4* __restrict__ W4) {
    int wid  = (blockIdx.x * blockDim.x + threadIdx.x) >> 5;   // row in [0, B*N)
    int lane = threadIdx.x & 31;
    float4 xr = x4[(size_t)wid * 32 + lane];
    float4 ws = W4[lane];
    float4 wd = W4[32 + lane];
    float a = xr.x * ws.x + xr.y * ws.y + xr.z * ws.z + xr.w * ws.w;
    float c = xr.x * wd.x + xr.y * wd.y + xr.z * wd.z + xr.w * wd.w;
    #pragma unroll
    for (int o = 16; o > 0; o >>= 1) {
        a += __shfl_xor_sync(0xFFFFFFFFu, a, o);
        c += __shfl_xor_sync(0xFFFFFFFFu, c, o);
    }
    if (lane == 0) {
        g_ssrc[wid] = a;
        g_sdst[wid] = c;
    }
}

// ---------------------------------------------------------------------------
// Main gather kernel: one warp per (b, n). Accumulate over CSR bucket of n:
//   out[b,n,:] = sum_{e: dst[e]==n} x[b, src[e], :] * sigmoid(ssrc + sdst + b)
// x[b] (2 MB) is L2-resident; writes are coalesced float4; no atomics.
// Block ordering is batch-major so co-resident CTAs share x[b] in L2.
// ---------------------------------------------------------------------------
__global__ void k_main(const float4* __restrict__ x4, const int* __restrict__ src,
                       const float* __restrict__ bias, float4* __restrict__ out4) {
    int wid  = (blockIdx.x * blockDim.x + threadIdx.x) >> 5;   // (b,n) pair
    int lane = threadIdx.x & 31;
    int b = wid >> 12;          // / NN
    int n = wid & (NN - 1);
    const float4* xb  = x4 + ((size_t)b * NN) * 32;
    const float*  ssb = g_ssrc + b * NN;
    float sd = g_sdst[wid] + bias[0];
    int lo = g_offsets[n], hi = g_offsets[n + 1];
    float4 acc = make_float4(0.f, 0.f, 0.f, 0.f);
    for (int j = lo; j < hi; j++) {
        int e = g_perm[j];                 // broadcast scalar load
        int s = src[e];                    // broadcast scalar load
        float z = ssb[s] + sd;
        float a = 1.0f / (1.0f + __expf(-z));
        float4 xs = xb[(size_t)s * 32 + lane];   // coalesced 512B per warp, L2 hit
        acc.x += xs.x * a;
        acc.y += xs.y * a;
        acc.z += xs.z * a;
        acc.w += xs.w * a;
    }
    out4[(size_t)wid * 32 + lane] = acc;
}

// ---------------------------------------------------------------------------
// Launch
// ---------------------------------------------------------------------------
extern "C" void kernel_launch(void* const* d_in, const int* in_sizes, int n_in,
                              void* d_out, int out_size) {
    const float* x    = (const float*)d_in[0];   // (B, N, D) f32
    const int*   ei   = (const int*)d_in[1];     // (2, E)    i32
    const float* W    = (const float*)d_in[2];   // (1, 2D)   f32
    const float* bias = (const float*)d_in[3];   // (1,)      f32
    float* out = (float*)d_out;                  // (B, N, D) f32

    const int* src = ei;        // edge_index[0]
    const int* dst = ei + EE;   // edge_index[1]

    k_zero_counts<<<(NN + 255) / 256, 256>>>();
    k_hist<<<(EE + 255) / 256, 256>>>(dst);
    k_scan<<<1, 1024>>>();
    k_scatter<<<(EE + 255) / 256, 256>>>(dst);
    k_sort_buckets<<<(NN + 255) / 256, 256>>>();
    k_dots<<<BN / 8, 256>>>((const float4*)x, (const float4*)W);
    k_main<<<BN / 8, 256>>>((const float4*)x, src, bias, (float4*)out);
}

// round 2
// speedup vs baseline: 1.1605x; 1.1605x over previous
#include <cuda_runtime.h>

// Problem constants (fixed by reference: B=32, N=4096, D=128, E=24576)
#define BB 32
#define NN 4096
#define DD 128
#define EE 24576
#define BN (BB * NN)

// Scratch (device globals: no allocation allowed in kernel_launch)
__device__ int   g_offsets[NN + 1];
__device__ int   g_perm[EE];
__device__ int   g_srcs[EE];      // src node per sorted CSR slot
__device__ int   g_dsts[EE];      // dst node per sorted CSR slot
__device__ float g_ssrc[BN];
__device__ float g_sdst[BN];      // includes bias
__device__ float g_att[(size_t)BB * EE];   // sigmoid gate per (b, slot)

// ---------------------------------------------------------------------------
// Fused CSR build over dst: histogram -> scan -> scatter -> per-bucket sort
// (deterministic order) -> emit per-slot src/dst. One block, 1024 threads.
// ---------------------------------------------------------------------------
__global__ void k_build(const int* __restrict__ src, const int* __restrict__ dst) {
    __shared__ int sh_cnt[NN];     // 16 KB: counts, then cursors
    __shared__ int sh_part[1024];  // 4 KB: scan partials
    int t = threadIdx.x;

    // zero counts
    #pragma unroll
    for (int i = t; i < NN; i += 1024) sh_cnt[i] = 0;
    __syncthreads();

    // histogram (shared atomics)
    for (int e = t; e < EE; e += 1024) atomicAdd(&sh_cnt[dst[e]], 1);
    __syncthreads();

    // exclusive scan of 4096 counts: 4 per thread + block scan of partials
    int base = t * 4;
    int v0 = sh_cnt[base + 0];
    int v1 = sh_cnt[base + 1];
    int v2 = sh_cnt[base + 2];
    int v3 = sh_cnt[base + 3];
    int s = v0 + v1 + v2 + v3;
    sh_part[t] = s;
    __syncthreads();
    for (int off = 1; off < 1024; off <<= 1) {
        int add = (t >= off) ? sh_part[t - off] : 0;
        __syncthreads();
        sh_part[t] += add;
        __syncthreads();
    }
    int run = sh_part[t] - s;
    int o0 = run; run += v0;
    int o1 = run; run += v1;
    int o2 = run; run += v2;
    int o3 = run; run += v3;
    int o4 = run;  // end of bucket base+3
    g_offsets[base + 0] = o0;
    g_offsets[base + 1] = o1;
    g_offsets[base + 2] = o2;
    g_offsets[base + 3] = o3;
    if (t == 1023) g_offsets[NN] = o4;  // == EE
    __syncthreads();

    // cursors (reuse sh_cnt)
    sh_cnt[base + 0] = o0;
    sh_cnt[base + 1] = o1;
    sh_cnt[base + 2] = o2;
    sh_cnt[base + 3] = o3;
    __syncthreads();

    // scatter edge ids into buckets (arbitrary intra-bucket order)
    for (int e = t; e < EE; e += 1024) {
        int pos = atomicAdd(&sh_cnt[dst[e]], 1);
        g_perm[pos] = e;
    }
    __syncthreads();  // CTA-scope fence: g_perm writes visible block-wide

    // deterministic order: insertion-sort each bucket by edge id (avg 6 elems)
    int lows[4]  = {o0, o1, o2, o3};
    int highs[4] = {o1, o2, o3, o4};
    #pragma unroll
    for (int k = 0; k < 4; k++) {
        int lo = lows[k], hi = highs[k];
        for (int i = lo + 1; i < hi; i++) {
            int key = g_perm[i];
            int j = i - 1;
            while (j >= lo && g_perm[j] > key) {
                g_perm[j + 1] = g_perm[j];
                j--;
            }
            g_perm[j + 1] = key;
        }
    }
    __syncthreads();

    // emit per-slot src/dst (removes double indirection from hot kernels)
    for (int j = t; j < EE; j += 1024) {
        int e = g_perm[j];
        g_srcs[j] = src[e];
        g_dsts[j] = dst[e];
    }
}

// ---------------------------------------------------------------------------
// Per-node projections: ssrc[b,n] = <x[b,n], Ws>, sdst[b,n] = <x[b,n], Wd>+bias.
// One warp per row; each lane owns one float4 (D=128 = 32 lanes * 4).
// ---------------------------------------------------------------------------
__global__ void k_dots(const float4* __restrict__ x4, const float4* __restrict__ W4,
                       const float* __restrict__ bias) {
    int wid  = (blockIdx.x * blockDim.x + threadIdx.x) >> 5;   // row in [0, B*N)
    int lane = threadIdx.x & 31;
    float4 xr = x4[(size_t)wid * 32 + lane];
    float4 ws = W4[lane];
    float4 wd = W4[32 + lane];
    float a = xr.x * ws.x + xr.y * ws.y + xr.z * ws.z + xr.w * ws.w;
    float c = xr.x * wd.x + xr.y * wd.y + xr.z * wd.z + xr.w * wd.w;
    #pragma unroll
    for (int o = 16; o > 0; o >>= 1) {
        a += __shfl_xor_sync(0xFFFFFFFFu, a, o);
        c += __shfl_xor_sync(0xFFFFFFFFu, c, o);
    }
    if (lane == 0) {
        g_ssrc[wid] = a;
        g_sdst[wid] = c + bias[0];
    }
}

// ---------------------------------------------------------------------------
// Attention precompute: att[b, j] = sigmoid(ssrc[b, srcs[j]] + sdst[b, dsts[j]])
// Edge-parallel over (b, slot); writes coalesced, gathers are 4B L2 hits.
// ---------------------------------------------------------------------------
__global__ void k_att() {
    int t = blockIdx.x * blockDim.x + threadIdx.x;   // [0, B*EE)
    int b = t / EE;
    int j = t - b * EE;
    int s = g_srcs[j];
    int n = g_dsts[j];
    float z = g_ssrc[b * NN + s] + g_sdst[b * NN + n];
    g_att[t] = 1.0f / (1.0f + __expf(-z));
}

// ---------------------------------------------------------------------------
// Main gather kernel: one warp per (b, n).
//   out[b,n,:] = sum_{slot j in bucket(n)} x[b, srcs[j], :] * att[b, j]
// Hot-loop chain is now a single L2 hop (srcs[j] -> x row); att[j] independent.
// 2-way unroll with dual accumulators for MLP. No atomics, coalesced writes.
// ---------------------------------------------------------------------------
__global__ void k_main(const float4* __restrict__ x4, float4* __restrict__ out4) {
    int wid  = (blockIdx.x * blockDim.x + threadIdx.x) >> 5;   // (b,n) pair
    int lane = threadIdx.x & 31;
    int b = wid >> 12;          // / NN
    int n = wid & (NN - 1);
    const float4* xb   = x4 + ((size_t)b * NN) * 32;
    const float*  attb = g_att + (size_t)b * EE;
    int lo = g_offsets[n], hi = g_offsets[n + 1];

    float4 acc0 = make_float4(0.f, 0.f, 0.f, 0.f);
    float4 acc1 = make_float4(0.f, 0.f, 0.f, 0.f);
    int j = lo;
    for (; j + 1 < hi; j += 2) {
        int   s0 = g_srcs[j];
        int   s1 = g_srcs[j + 1];
        float a0 = attb[j];
        float a1 = attb[j + 1];
        float4 v0 = xb[(size_t)s0 * 32 + lane];
        float4 v1 = xb[(size_t)s1 * 32 + lane];
        acc0.x += v0.x * a0; acc0.y += v0.y * a0; acc0.z += v0.z * a0; acc0.w += v0.w * a0;
        acc1.x += v1.x * a1; acc1.y += v1.y * a1; acc1.z += v1.z * a1; acc1.w += v1.w * a1;
    }
    if (j < hi) {
        int   s0 = g_srcs[j];
        float a0 = attb[j];
        float4 v0 = xb[(size_t)s0 * 32 + lane];
        acc0.x += v0.x * a0; acc0.y += v0.y * a0; acc0.z += v0.z * a0; acc0.w += v0.w * a0;
    }
    acc0.x += acc1.x; acc0.y += acc1.y; acc0.z += acc1.z; acc0.w += acc1.w;
    out4[(size_t)wid * 32 + lane] = acc0;
}

// ---------------------------------------------------------------------------
// Launch
// ---------------------------------------------------------------------------
extern "C" void kernel_launch(void* const* d_in, const int* in_sizes, int n_in,
                              void* d_out, int out_size) {
    const float* x    = (const float*)d_in[0];   // (B, N, D) f32
    const int*   ei   = (const int*)d_in[1];     // (2, E)    i32
    const float* W    = (const float*)d_in[2];   // (1, 2D)   f32
    const float* bias = (const float*)d_in[3];   // (1,)      f32
    float* out = (float*)d_out;                  // (B, N, D) f32

    const int* src = ei;        // edge_index[0]
    const int* dst = ei + EE;   // edge_index[1]

    k_build<<<1, 1024>>>(src, dst);
    k_dots<<<BN / 8, 256>>>((const float4*)x, (const float4*)W, bias);
    k_att<<<(BB * EE) / 256, 256>>>();
    k_main<<<BN / 8, 256>>>((const float4*)x, (float4*)out);
}

// round 3
// speedup vs baseline: 1.2879x; 1.1098x over previous
#include <cuda_runtime.h>
#include <stdint.h>

// Problem constants (fixed by reference: B=32, N=4096, D=128, E=24576)
#define BB 32
#define NN 4096
#define DD 128
#define EE 24576
#define BN (BB * NN)

// Scratch (device globals: no allocation allowed in kernel_launch)
__device__ int   g_offsets[NN + 1];
__device__ int   g_srcs[EE];      // src node per sorted CSR slot
__device__ float g_ssrc[BN];
__device__ float g_sdst[BN];      // includes bias

// ---------------------------------------------------------------------------
// Fused CSR build over dst, entirely in shared memory:
// histogram -> scan -> scatter -> per-bucket insertion sort (deterministic,
// by edge id) -> emit per-slot src. One block, 1024 threads, 68KB dyn smem.
// ---------------------------------------------------------------------------
__global__ void k_build(const int* __restrict__ src, const int* __restrict__ dst) {
    extern __shared__ int sh[];
    int*      sh_cnt  = sh;                              // [NN]   16 KB
    int*      sh_part = sh + NN;                         // [1024]  4 KB
    uint16_t* sh_perm = (uint16_t*)(sh + NN + 1024);     // [EE]   48 KB
    int t = threadIdx.x;

    // zero counts
    #pragma unroll
    for (int i = t; i < NN; i += 1024) sh_cnt[i] = 0;
    __syncthreads();

    // histogram (shared atomics)
    #pragma unroll
    for (int e = t; e < EE; e += 1024) atomicAdd(&sh_cnt[dst[e]], 1);
    __syncthreads();

    // exclusive scan of 4096 counts: 4 per thread + block scan of partials
    int base = t * 4;
    int v0 = sh_cnt[base + 0];
    int v1 = sh_cnt[base + 1];
    int v2 = sh_cnt[base + 2];
    int v3 = sh_cnt[base + 3];
    int s = v0 + v1 + v2 + v3;
    sh_part[t] = s;
    __syncthreads();
    for (int off = 1; off < 1024; off <<= 1) {
        int add = (t >= off) ? sh_part[t - off] : 0;
        __syncthreads();
        sh_part[t] += add;
        __syncthreads();
    }
    int run = sh_part[t] - s;
    int o0 = run; run += v0;
    int o1 = run; run += v1;
    int o2 = run; run += v2;
    int o3 = run; run += v3;
    int o4 = run;
    g_offsets[base + 0] = o0;
    g_offsets[base + 1] = o1;
    g_offsets[base + 2] = o2;
    g_offsets[base + 3] = o3;
    if (t == 1023) g_offsets[NN] = o4;  // == EE
    __syncthreads();

    // cursors (reuse sh_cnt)
    sh_cnt[base + 0] = o0;
    sh_cnt[base + 1] = o1;
    sh_cnt[base + 2] = o2;
    sh_cnt[base + 3] = o3;
    __syncthreads();

    // scatter edge ids into smem buckets (arbitrary intra-bucket order)
    #pragma unroll
    for (int e = t; e < EE; e += 1024) {
        int pos = atomicAdd(&sh_cnt[dst[e]], 1);
        sh_perm[pos] = (uint16_t)e;
    }
    __syncthreads();

    // deterministic order: insertion-sort each bucket by edge id (avg 6 elems)
    int lows[4]  = {o0, o1, o2, o3};
    int highs[4] = {o1, o2, o3, o4};
    #pragma unroll
    for (int k = 0; k < 4; k++) {
        int lo = lows[k], hi = highs[k];
        for (int i = lo + 1; i < hi; i++) {
            uint16_t key = sh_perm[i];
            int j = i - 1;
            while (j >= lo && sh_perm[j] > key) {
                sh_perm[j + 1] = sh_perm[j];
                j--;
            }
            sh_perm[j + 1] = key;
        }
    }
    __syncthreads();

    // emit per-slot src (coalesced global writes)
    #pragma unroll
    for (int j = t; j < EE; j += 1024) {
        g_srcs[j] = src[(int)sh_perm[j]];
    }
}

// ---------------------------------------------------------------------------
// Per-node projections: ssrc[b,n] = <x[b,n], Ws>, sdst[b,n] = <x[b,n], Wd>+bias.
// One warp per row; each lane owns one float4 (D=128 = 32 lanes * 4).
// ---------------------------------------------------------------------------
__global__ void k_dots(const float4* __restrict__ x4, const float4* __restrict__ W4,
                       const float* __restrict__ bias) {
    int wid  = (blockIdx.x * blockDim.x + threadIdx.x) >> 5;   // row in [0, B*N)
    int lane = threadIdx.x & 31;
    float4 xr = x4[(size_t)wid * 32 + lane];
    float4 ws = W4[lane];
    float4 wd = W4[32 + lane];
    float a = xr.x * ws.x + xr.y * ws.y + xr.z * ws.z + xr.w * ws.w;
    float c = xr.x * wd.x + xr.y * wd.y + xr.z * wd.z + xr.w * wd.w;
    #pragma unroll
    for (int o = 16; o > 0; o >>= 1) {
        a += __shfl_xor_sync(0xFFFFFFFFu, a, o);
        c += __shfl_xor_sync(0xFFFFFFFFu, c, o);
    }
    if (lane == 0) {
        g_ssrc[wid] = a;
        g_sdst[wid] = c + bias[0];
    }
}

__device__ __forceinline__ float sigmoidf_fast(float z) {
    return 1.0f / (1.0f + __expf(-z));
}

// ---------------------------------------------------------------------------
// Main gather kernel: one warp per (n, batch-pair). Each warp handles batches
// b and b+16 for node n, sharing all index loads:
//   out[b,n,:] = sum_{slot j in bucket(n)} x[b, srcs[j], :] *
//                sigmoid(ssrc[b, srcs[j]] + sdst[b, n])
// 2-edge unroll x 2 batches = 4 independent gather chains per warp.
// No atomics, coalesced float4 writes.
// ---------------------------------------------------------------------------
__global__ void __launch_bounds__(256) k_main(const float4* __restrict__ x4,
                                              float4* __restrict__ out4) {
    int w    = (blockIdx.x * blockDim.x + threadIdx.x) >> 5;   // [0, 16*NN)
    int lane = threadIdx.x & 31;
    int n  = w & (NN - 1);
    int b0 = w >> 12;           // [0,16)
    int b1 = b0 + 16;

    const float4* xb0 = x4 + ((size_t)b0 * NN) * 32;
    const float4* xb1 = x4 + ((size_t)b1 * NN) * 32;
    const float*  ss0 = g_ssrc + b0 * NN;
    const float*  ss1 = g_ssrc + b1 * NN;
    float sd0 = g_sdst[b0 * NN + n];
    float sd1 = g_sdst[b1 * NN + n];

    int lo = g_offsets[n], hi = g_offsets[n + 1];

    float4 p0 = make_float4(0.f, 0.f, 0.f, 0.f);   // acc b0, edge-lane 0
    float4 p1 = make_float4(0.f, 0.f, 0.f, 0.f);   // acc b0, edge-lane 1
    float4 q0 = make_float4(0.f, 0.f, 0.f, 0.f);   // acc b1, edge-lane 0
    float4 q1 = make_float4(0.f, 0.f, 0.f, 0.f);   // acc b1, edge-lane 1

    int j = lo;
    for (; j + 1 < hi; j += 2) {
        int s0 = g_srcs[j];
        int s1 = g_srcs[j + 1];
        float a00 = sigmoidf_fast(ss0[s0] + sd0);
        float a10 = sigmoidf_fast(ss1[s0] + sd1);
        float a01 = sigmoidf_fast(ss0[s1] + sd0);
        float a11 = sigmoidf_fast(ss1[s1] + sd1);
        float4 v00 = xb0[(size_t)s0 * 32 + lane];
        float4 v10 = xb1[(size_t)s0 * 32 + lane];
        float4 v01 = xb0[(size_t)s1 * 32 + lane];
        float4 v11 = xb1[(size_t)s1 * 32 + lane];
        p0.x += v00.x * a00; p0.y += v00.y * a00; p0.z += v00.z * a00; p0.w += v00.w * a00;
        q0.x += v10.x * a10; q0.y += v10.y * a10; q0.z += v10.z * a10; q0.w += v10.w * a10;
        p1.x += v01.x * a01; p1.y += v01.y * a01; p1.z += v01.z * a01; p1.w += v01.w * a01;
        q1.x += v11.x * a11; q1.y += v11.y * a11; q1.z += v11.z * a11; q1.w += v11.w * a11;
    }
    if (j < hi) {
        int s0 = g_srcs[j];
        float a00 = sigmoidf_fast(ss0[s0] + sd0);
        float a10 = sigmoidf_fast(ss1[s0] + sd1);
        float4 v00 = xb0[(size_t)s0 * 32 + lane];
        float4 v10 = xb1[(size_t)s0 * 32 + lane];
        p0.x += v00.x * a00; p0.y += v00.y * a00; p0.z += v00.z * a00; p0.w += v00.w * a00;
        q0.x += v10.x * a10; q0.y += v10.y * a10; q0.z += v10.z * a10; q0.w += v10.w * a10;
    }
    p0.x += p1.x; p0.y += p1.y; p0.z += p1.z; p0.w += p1.w;
    q0.x += q1.x; q0.y += q1.y; q0.z += q1.z; q0.w += q1.w;

    out4[((size_t)b0 * NN + n) * 32 + lane] = p0;
    out4[((size_t)b1 * NN + n) * 32 + lane] = q0;
}

// ---------------------------------------------------------------------------
// Launch
// ---------------------------------------------------------------------------
extern "C" void kernel_launch(void* const* d_in, const int* in_sizes, int n_in,
                              void* d_out, int out_size) {
    const float* x    = (const float*)d_in[0];   // (B, N, D) f32
    const int*   ei   = (const int*)d_in[1];     // (2, E)    i32
    const float* W    = (const float*)d_in[2];   // (1, 2D)   f32
    const float* bias = (const float*)d_in[3];   // (1,)      f32
    float* out = (float*)d_out;                  // (B, N, D) f32

    const int* src = ei;        // edge_index[0]
    const int* dst = ei + EE;   // edge_index[1]

    const int build_smem = NN * 4 + 1024 * 4 + EE * 2;   // 68 KB
    static bool attr_set = false;
    if (!attr_set) {
        cudaFuncSetAttribute(k_build, cudaFuncAttributeMaxDynamicSharedMemorySize,
                             build_smem);
        attr_set = true;
    }

    k_build<<<1, 1024, build_smem>>>(src, dst);
    k_dots<<<BN / 8, 256>>>((const float4*)x, (const float4*)W, bias);
    k_main<<<(16 * NN) / 8, 256>>>((const float4*)x, (float4*)out);
}

// round 4
// speedup vs baseline: 1.4519x; 1.1273x over previous
#include <cuda_runtime.h>
#include <stdint.h>

// Problem constants (fixed by reference: B=32, N=4096, D=128, E=24576)
#define BB 32
#define NN 4096
#define DD 128
#define EE 24576
#define BN (BB * NN)
#define NCHUNK 24          // EE / 1024

// Scratch (device globals: no allocation allowed in kernel_launch)
__device__ int   g_cnt[NCHUNK * NN];    // per-(chunk, node) histogram
__device__ int   g_tot[NN];             // per-node totals
__device__ int   g_base[NCHUNK * NN];   // per-(chunk, node) scatter base
__device__ int   g_offsets[NN + 1];
__device__ int   g_srcs[EE];            // src node per CSR slot (edge-id order)
__device__ float g_ssrc[BN];
__device__ float g_sdst[BN];            // includes bias

// ---------------------------------------------------------------------------
// kA: per-chunk histogram. Block c owns edges [1024c, 1024c+1024).
// ---------------------------------------------------------------------------
__global__ void kA_hist(const int* __restrict__ dst) {
    __shared__ int h[NN];
    int c = blockIdx.x, t = threadIdx.x;
    #pragma unroll
    for (int i = t; i < NN; i += 1024) h[i] = 0;
    __syncthreads();
    atomicAdd(&h[dst[c * 1024 + t]], 1);
    __syncthreads();
    #pragma unroll
    for (int i = t; i < NN; i += 1024) g_cnt[c * NN + i] = h[i];
}

// ---------------------------------------------------------------------------
// kB: per-node totals (coalesced column sums). grid 16 x 256.
// ---------------------------------------------------------------------------
__global__ void kB_totals() {
    int n = blockIdx.x * 256 + threadIdx.x;
    int s = 0;
    #pragma unroll
    for (int c = 0; c < NCHUNK; c++) s += g_cnt[c * NN + n];
    g_tot[n] = s;
}

// ---------------------------------------------------------------------------
// kC: exclusive scan of 4096 totals -> offsets. One block, 1024 threads.
// ---------------------------------------------------------------------------
__global__ void kC_scan() {
    __shared__ int sh[1024];
    int t = threadIdx.x;
    int base = t * 4;
    int v0 = g_tot[base + 0];
    int v1 = g_tot[base + 1];
    int v2 = g_tot[base + 2];
    int v3 = g_tot[base + 3];
    int s = v0 + v1 + v2 + v3;
    sh[t] = s;
    __syncthreads();
    for (int off = 1; off < 1024; off <<= 1) {
        int add = (t >= off) ? sh[t - off] : 0;
        __syncthreads();
        sh[t] += add;
        __syncthreads();
    }
    int run = sh[t] - s;
    g_offsets[base + 0] = run; run += v0;
    g_offsets[base + 1] = run; run += v1;
    g_offsets[base + 2] = run; run += v2;
    g_offsets[base + 3] = run; run += v3;
    if (t == 1023) g_offsets[NN] = run;  // == EE
}

// ---------------------------------------------------------------------------
// kD: per-(chunk, node) scatter bases (coalesced). grid 16 x 256.
// ---------------------------------------------------------------------------
__global__ void kD_bases() {
    int n = blockIdx.x * 256 + threadIdx.x;
    int run = g_offsets[n];
    #pragma unroll
    for (int c = 0; c < NCHUNK; c++) {
        g_base[c * NN + n] = run;
        run += g_cnt[c * NN + n];
    }
}

// ---------------------------------------------------------------------------
// kE: ordered scatter -> g_srcs in exact edge-id order (deterministic).
// In-warp rank via match_any; in-block order via 32 serialized warp rounds;
// cross-chunk order via g_base. No sort needed.
// ---------------------------------------------------------------------------
__global__ void kE_scatter(const int* __restrict__ src, const int* __restrict__ dst) {
    __shared__ int cur[NN];
    int c = blockIdx.x, t = threadIdx.x;
    int e = c * 1024 + t;
    int d  = dst[e];
    int sv = src[e];

    // lazy cursor init: only nodes present in this chunk (same-value races benign)
    cur[d] = g_base[c * NN + d];
    __syncthreads();

    unsigned mask   = __match_any_sync(0xFFFFFFFFu, d);
    int lane        = t & 31;
    int lanerank    = __popc(mask & ((1u << lane) - 1));
    int cnt         = __popc(mask);
    int leader      = __ffs(mask) - 1;
    int wid         = t >> 5;

    int base = 0;
    #pragma unroll
    for (int w = 0; w < 32; w++) {
        if (wid == w && lane == leader) {
            base = cur[d];          // distinct d per leader within a warp
            cur[d] = base + cnt;
        }
        __syncthreads();
    }
    base = __shfl_sync(0xFFFFFFFFu, base, leader);
    g_srcs[base + lanerank] = sv;
}

// ---------------------------------------------------------------------------
// Per-node projections: ssrc[b,n] = <x[b,n], Ws>, sdst[b,n] = <x[b,n], Wd>+bias.
// One warp per row; each lane owns one float4 (D=128 = 32 lanes * 4).
// ---------------------------------------------------------------------------
__global__ void k_dots(const float4* __restrict__ x4, const float4* __restrict__ W4,
                       const float* __restrict__ bias) {
    int wid  = (blockIdx.x * blockDim.x + threadIdx.x) >> 5;   // row in [0, B*N)
    int lane = threadIdx.x & 31;
    float4 xr = x4[(size_t)wid * 32 + lane];
    float4 ws = W4[lane];
    float4 wd = W4[32 + lane];
    float a = xr.x * ws.x + xr.y * ws.y + xr.z * ws.z + xr.w * ws.w;
    float c = xr.x * wd.x + xr.y * wd.y + xr.z * wd.z + xr.w * wd.w;
    #pragma unroll
    for (int o = 16; o > 0; o >>= 1) {
        a += __shfl_xor_sync(0xFFFFFFFFu, a, o);
        c += __shfl_xor_sync(0xFFFFFFFFu, c, o);
    }
    if (lane == 0) {
        g_ssrc[wid] = a;
        g_sdst[wid] = c + bias[0];
    }
}

__device__ __forceinline__ float sigmoidf_fast(float z) {
    return 1.0f / (1.0f + __expf(-z));
}

// ---------------------------------------------------------------------------
// Main gather kernel: one warp per (n, batch-pair b, b+16). Shared index
// loads, 2-edge x 2-batch loads in flight, single accumulator per batch
// (FFMA chain 16cyc << load latency; fewer regs -> higher occupancy).
// ---------------------------------------------------------------------------
__global__ void __launch_bounds__(256) k_main(const float4* __restrict__ x4,
                                              float4* __restrict__ out4) {
    int w    = (blockIdx.x * blockDim.x + threadIdx.x) >> 5;   // [0, 16*NN)
    int lane = threadIdx.x & 31;
    int n  = w & (NN - 1);
    int b0 = w >> 12;           // [0,16)
    int b1 = b0 + 16;

    const float4* xb0 = x4 + ((size_t)b0 * NN) * 32;
    const float4* xb1 = x4 + ((size_t)b1 * NN) * 32;
    const float*  ss0 = g_ssrc + b0 * NN;
    const float*  ss1 = g_ssrc + b1 * NN;
    float sd0 = g_sdst[b0 * NN + n];
    float sd1 = g_sdst[b1 * NN + n];

    int lo = g_offsets[n], hi = g_offsets[n + 1];

    float4 p = make_float4(0.f, 0.f, 0.f, 0.f);   // acc b0
    float4 q = make_float4(0.f, 0.f, 0.f, 0.f);   // acc b1

    int j = lo;
    for (; j + 1 < hi; j += 2) {
        int s0 = g_srcs[j];
        int s1 = g_srcs[j + 1];
        float a00 = sigmoidf_fast(ss0[s0] + sd0);
        float a10 = sigmoidf_fast(ss1[s0] + sd1);
        float a01 = sigmoidf_fast(ss0[s1] + sd0);
        float a11 = sigmoidf_fast(ss1[s1] + sd1);
        float4 v00 = xb0[(size_t)s0 * 32 + lane];
        float4 v10 = xb1[(size_t)s0 * 32 + lane];
        float4 v01 = xb0[(size_t)s1 * 32 + lane];
        float4 v11 = xb1[(size_t)s1 * 32 + lane];
        p.x += v00.x * a00; p.y += v00.y * a00; p.z += v00.z * a00; p.w += v00.w * a00;
        q.x += v10.x * a10; q.y += v10.y * a10; q.z += v10.z * a10; q.w += v10.w * a10;
        p.x += v01.x * a01; p.y += v01.y * a01; p.z += v01.z * a01; p.w += v01.w * a01;
        q.x += v11.x * a11; q.y += v11.y * a11; q.z += v11.z * a11; q.w += v11.w * a11;
    }
    if (j < hi) {
        int s0 = g_srcs[j];
        float a00 = sigmoidf_fast(ss0[s0] + sd0);
        float a10 = sigmoidf_fast(ss1[s0] + sd1);
        float4 v00 = xb0[(size_t)s0 * 32 + lane];
        float4 v10 = xb1[(size_t)s0 * 32 + lane];
        p.x += v00.x * a00; p.y += v00.y * a00; p.z += v00.z * a00; p.w += v00.w * a00;
        q.x += v10.x * a10; q.y += v10.y * a10; q.z += v10.z * a10; q.w += v10.w * a10;
    }

    out4[((size_t)b0 * NN + n) * 32 + lane] = p;
    out4[((size_t)b1 * NN + n) * 32 + lane] = q;
}

// ---------------------------------------------------------------------------
// Launch
// ---------------------------------------------------------------------------
extern "C" void kernel_launch(void* const* d_in, const int* in_sizes, int n_in,
                              void* d_out, int out_size) {
    const float* x    = (const float*)d_in[0];   // (B, N, D) f32
    const int*   ei   = (const int*)d_in[1];     // (2, E)    i32
    const float* W    = (const float*)d_in[2];   // (1, 2D)   f32
    const float* bias = (const float*)d_in[3];   // (1,)      f32
    float* out = (float*)d_out;                  // (B, N, D) f32

    const int* src = ei;        // edge_index[0]
    const int* dst = ei + EE;   // edge_index[1]

    kA_hist<<<NCHUNK, 1024>>>(dst);
    kB_totals<<<NN / 256, 256>>>();
    kC_scan<<<1, 1024>>>();
    kD_bases<<<NN / 256, 256>>>();
    kE_scatter<<<NCHUNK, 1024>>>(src, dst);
    k_dots<<<BN / 8, 256>>>((const float4*)x, (const float4*)W, bias);
    k_main<<<(16 * NN) / 8, 256>>>((const float4*)x, (float4*)out);
}

// round 5
// speedup vs baseline: 1.5292x; 1.0532x over previous
#include <cuda_runtime.h>
#include <stdint.h>

// Problem constants (fixed by reference: B=32, N=4096, D=128, E=24576)
#define BB 32
#define NN 4096
#define DD 128
#define EE 24576
#define BN (BB * NN)
#define NCHUNK 24          // EE / 1024

// Scratch (device globals: no allocation allowed in kernel_launch)
__device__ int   g_cnt[NCHUNK * NN];    // per-(chunk, node) histogram
__device__ int   g_offsets[NN + 1];
__device__ int   g_srcs[EE];            // src node per CSR slot (edge-id order)
__device__ float g_ssrc[BN];
__device__ float g_sdst[BN];            // includes bias

// ---------------------------------------------------------------------------
// kA: per-chunk histogram. Block c owns edges [1024c, 1024c+1024).
// ---------------------------------------------------------------------------
__global__ void kA_hist(const int* __restrict__ dst) {
    __shared__ int h[NN];
    int c = blockIdx.x, t = threadIdx.x;
    #pragma unroll
    for (int i = t; i < NN; i += 1024) h[i] = 0;
    __syncthreads();
    atomicAdd(&h[dst[c * 1024 + t]], 1);
    __syncthreads();
    #pragma unroll
    for (int i = t; i < NN; i += 1024) g_cnt[c * NN + i] = h[i];
}

// ---------------------------------------------------------------------------
// k_build2: fused totals + scan + per-chunk bases + deterministic scatter.
// 24 blocks; block c scatters chunk c. Each block redundantly computes node
// totals (for the scan) and the chunk-prefix (for its cursors) in one
// coalesced pass over g_cnt, so no cross-kernel dependency chain remains.
// Output g_srcs is in exact edge-id order within each dst bucket.
// ---------------------------------------------------------------------------
__global__ void k_build2(const int* __restrict__ src, const int* __restrict__ dst) {
    __shared__ int offs[NN];       // exclusive offsets -> then cursors for chunk c
    __shared__ int part[1024];
    int c = blockIdx.x, t = threadIdx.x;
    int base = t * 4;

    // totals + prefix-below-c for this thread's 4 nodes (coalesced loads)
    int tot[4] = {0, 0, 0, 0};
    int pre[4] = {0, 0, 0, 0};
    #pragma unroll
    for (int cc = 0; cc < NCHUNK; cc++) {
        #pragma unroll
        for (int k = 0; k < 4; k++) {
            int v = g_cnt[cc * NN + base + k];
            tot[k] += v;
            if (cc < c) pre[k] += v;
        }
    }

    // block-wide exclusive scan of totals
    int s = tot[0] + tot[1] + tot[2] + tot[3];
    part[t] = s;
    __syncthreads();
    for (int off = 1; off < 1024; off <<= 1) {
        int add = (t >= off) ? part[t - off] : 0;
        __syncthreads();
        part[t] += add;
        __syncthreads();
    }
    int run = part[t] - s;
    #pragma unroll
    for (int k = 0; k < 4; k++) {
        if (c == 0) g_offsets[base + k] = run;
        offs[base + k] = run + pre[k];   // this chunk's cursor for node base+k
        run += tot[k];
    }
    if (c == 0 && t == 1023) g_offsets[NN] = run;  // == EE
    __syncthreads();

    // deterministic scatter of chunk c: in-warp rank via match_any,
    // in-block order via 32 serialized warp rounds, cross-chunk via pre[].
    int e  = c * 1024 + t;
    int d  = dst[e];
    int sv = src[e];
    unsigned mask = __match_any_sync(0xFFFFFFFFu, d);
    int lane     = t & 31;
    int lanerank = __popc(mask & ((1u << lane) - 1));
    int cntm     = __popc(mask);
    int leader   = __ffs(mask) - 1;
    int wid      = t >> 5;

    int bpos = 0;
    #pragma unroll
    for (int w = 0; w < 32; w++) {
        if (wid == w && lane == leader) {
            bpos = offs[d];
            offs[d] = bpos + cntm;
        }
        __syncthreads();
    }
    bpos = __shfl_sync(0xFFFFFFFFu, bpos, leader);
    g_srcs[bpos + lanerank] = sv;
}

// ---------------------------------------------------------------------------
// Per-node projections: ssrc[b,n] = <x[b,n], Ws>, sdst[b,n] = <x[b,n], Wd>+bias.
// One warp per row; each lane owns one float4 (D=128 = 32 lanes * 4).
// ---------------------------------------------------------------------------
__global__ void k_dots(const float4* __restrict__ x4, const float4* __restrict__ W4,
                       const float* __restrict__ bias) {
    int wid  = (blockIdx.x * blockDim.x + threadIdx.x) >> 5;   // row in [0, B*N)
    int lane = threadIdx.x & 31;
    float4 xr = x4[(size_t)wid * 32 + lane];
    float4 ws = W4[lane];
    float4 wd = W4[32 + lane];
    float a = xr.x * ws.x + xr.y * ws.y + xr.z * ws.z + xr.w * ws.w;
    float c = xr.x * wd.x + xr.y * wd.y + xr.z * wd.z + xr.w * wd.w;
    #pragma unroll
    for (int o = 16; o > 0; o >>= 1) {
        a += __shfl_xor_sync(0xFFFFFFFFu, a, o);
        c += __shfl_xor_sync(0xFFFFFFFFu, c, o);
    }
    if (lane == 0) {
        g_ssrc[wid] = a;
        g_sdst[wid] = c + bias[0];
    }
}

__device__ __forceinline__ float sigmoidf_fast(float z) {
    return 1.0f / (1.0f + __expf(-z));
}

// ---------------------------------------------------------------------------
// Main gather kernel: one warp per (n, batch-pair b, b+16). Shared index
// loads, 2-edge x 2-batch loads in flight. Out rows are written with __stcs
// (evict-first) so the 67MB write stream doesn't evict L2-resident x.
// ---------------------------------------------------------------------------
__global__ void __launch_bounds__(256) k_main(const float4* __restrict__ x4,
                                              float4* __restrict__ out4) {
    int w    = (blockIdx.x * blockDim.x + threadIdx.x) >> 5;   // [0, 16*NN)
    int lane = threadIdx.x & 31;
    int n  = w & (NN - 1);
    int b0 = w >> 12;           // [0,16)
    int b1 = b0 + 16;

    const float4* xb0 = x4 + ((size_t)b0 * NN) * 32;
    const float4* xb1 = x4 + ((size_t)b1 * NN) * 32;
    const float*  ss0 = g_ssrc + b0 * NN;
    const float*  ss1 = g_ssrc + b1 * NN;
    float sd0 = g_sdst[b0 * NN + n];
    float sd1 = g_sdst[b1 * NN + n];

    int lo = g_offsets[n], hi = g_offsets[n + 1];

    float4 p = make_float4(0.f, 0.f, 0.f, 0.f);   // acc b0
    float4 q = make_float4(0.f, 0.f, 0.f, 0.f);   // acc b1

    int j = lo;
    for (; j + 1 < hi; j += 2) {
        int s0 = g_srcs[j];
        int s1 = g_srcs[j + 1];
        float a00 = sigmoidf_fast(ss0[s0] + sd0);
        float a10 = sigmoidf_fast(ss1[s0] + sd1);
        float a01 = sigmoidf_fast(ss0[s1] + sd0);
        float a11 = sigmoidf_fast(ss1[s1] + sd1);
        float4 v00 = xb0[(size_t)s0 * 32 + lane];
        float4 v10 = xb1[(size_t)s0 * 32 + lane];
        float4 v01 = xb0[(size_t)s1 * 32 + lane];
        float4 v11 = xb1[(size_t)s1 * 32 + lane];
        p.x += v00.x * a00; p.y += v00.y * a00; p.z += v00.z * a00; p.w += v00.w * a00;
        q.x += v10.x * a10; q.y += v10.y * a10; q.z += v10.z * a10; q.w += v10.w * a10;
        p.x += v01.x * a01; p.y += v01.y * a01; p.z += v01.z * a01; p.w += v01.w * a01;
        q.x += v11.x * a11; q.y += v11.y * a11; q.z += v11.z * a11; q.w += v11.w * a11;
    }
    if (j < hi) {
        int s0 = g_srcs[j];
        float a00 = sigmoidf_fast(ss0[s0] + sd0);
        float a10 = sigmoidf_fast(ss1[s0] + sd1);
        float4 v00 = xb0[(size_t)s0 * 32 + lane];
        float4 v10 = xb1[(size_t)s0 * 32 + lane];
        p.x += v00.x * a00; p.y += v00.y * a00; p.z += v00.z * a00; p.w += v00.w * a00;
        q.x += v10.x * a10; q.y += v10.y * a10; q.z += v10.z * a10; q.w += v10.w * a10;
    }

    __stcs(&out4[((size_t)b0 * NN + n) * 32 + lane], p);
    __stcs(&out4[((size_t)b1 * NN + n) * 32 + lane], q);
}

// ---------------------------------------------------------------------------
// Launch
// ---------------------------------------------------------------------------
extern "C" void kernel_launch(void* const* d_in, const int* in_sizes, int n_in,
                              void* d_out, int out_size) {
    const float* x    = (const float*)d_in[0];   // (B, N, D) f32
    const int*   ei   = (const int*)d_in[1];     // (2, E)    i32
    const float* W    = (const float*)d_in[2];   // (1, 2D)   f32
    const float* bias = (const float*)d_in[3];   // (1,)      f32
    float* out = (float*)d_out;                  // (B, N, D) f32

    const int* src = ei;        // edge_index[0]
    const int* dst = ei + EE;   // edge_index[1]

    kA_hist<<<NCHUNK, 1024>>>(dst);
    k_build2<<<NCHUNK, 1024>>>(src, dst);
    k_dots<<<BN / 8, 256>>>((const float4*)x, (const float4*)W, bias);
    k_main<<<(16 * NN) / 8, 256>>>((const float4*)x, (float4*)out);
}